// round 1
// baseline (speedup 1.0000x reference)
#include <cuda_runtime.h>
#include <math.h>

#define NN 50000
#define EE 250000
#define DD 128
#define FF 12
#define LL 4
#define TE 64

// Persistent scratch (no allocations allowed)
__device__ float g_x[NN * DD];
__device__ float g_p[NN * 2];
__device__ float g_agg[NN * DD];
__device__ float g_dp[NN * 2];

typedef unsigned long long u64;

__device__ __forceinline__ float silu(float z) {
    return z / (1.0f + __expf(-z));
}

__device__ __forceinline__ u64 pack2(float lo, float hi) {
    u64 r;
    asm("mov.b64 %0, {%1, %2};" : "=l"(r) : "f"(lo), "f"(hi));
    return r;
}
__device__ __forceinline__ u64 fma2(u64 a, u64 b, u64 c) {
    u64 d;
    asm("fma.rn.f32x2 %0, %1, %2, %3;" : "=l"(d) : "l"(a), "l"(b), "l"(c));
    return d;
}
__device__ __forceinline__ float2 unpack2(u64 v) {
    float2 r;
    asm("mov.b64 {%0, %1}, %2;" : "=f"(r.x), "=f"(r.y) : "l"(v));
    return r;
}

// ---------------------------------------------------------------------------
// x = node_features @ Wp + bp ;  p = pos
// ---------------------------------------------------------------------------
__global__ void init_kernel(const float* __restrict__ nf, const float* __restrict__ pos,
                            const float* __restrict__ Wp, const float* __restrict__ bp) {
    int n = blockIdx.x;
    int d = threadIdx.x;
    __shared__ float s_nf[FF];
    if (d < FF) s_nf[d] = nf[n * FF + d];
    __syncthreads();
    float acc = bp[d];
#pragma unroll
    for (int f = 0; f < FF; f++) acc = fmaf(s_nf[f], Wp[f * DD + d], acc);
    g_x[n * DD + d] = acc;
    if (d < 2) g_p[n * 2 + d] = pos[n * 2 + d];
}

// ---------------------------------------------------------------------------
// Edge kernel: per 64-edge tile
//   e_in = [x[src], x[tgt], dist]  (K-major in smem AT[257][68])
//   H = silu(e_in @ W1 + b1); msg = H @ W2 + b2
//   pw = silu([msg,dist] @ pw1 + pb1)*pw2 + pb2
//   atomic: agg[tgt] += msg ; dp[tgt] += pos_unit * pw
// ---------------------------------------------------------------------------
#define AT_STR 68
#define SM_AT (257 * AT_STR)
#define SM_BS (32 * 128)

__global__ void __launch_bounds__(256, 2) edge_kernel(
    const float* __restrict__ W1, const float* __restrict__ b1,
    const float* __restrict__ W2, const float* __restrict__ b2,
    const float* __restrict__ pw1, const float* __restrict__ pb1,
    const float* __restrict__ pw2, const float* __restrict__ pb2,
    const int* __restrict__ eidx)
{
    extern __shared__ float sm[];
    float* AT = sm;                    // [257][68]  reused for H_T [128][68], M_T [128][68]
    float* Bs = sm + SM_AT;            // [32][128]
    float* s_dist = Bs + SM_BS;        // [64]
    float* s_pux = s_dist + TE;        // [64]
    float* s_puy = s_pux + TE;         // [64]
    int* s_src = (int*)(s_puy + TE);   // [64]
    int* s_tgt = s_src + TE;           // [64]

    const int tid = threadIdx.x;
    const int e0 = blockIdx.x * TE;

    if (tid < TE) {
        int ge = e0 + tid;
        int src = 0, tgt = 0;
        if (ge < EE) { src = eidx[ge]; tgt = eidx[EE + ge]; }
        s_src[tid] = src;
        s_tgt[tid] = tgt;
        float2 ps = *(const float2*)&g_p[src * 2];
        float2 pt = *(const float2*)&g_p[tgt * 2];
        float dx = pt.x - ps.x, dy = pt.y - ps.y;
        float d = sqrtf(dx * dx + dy * dy);
        s_dist[tid] = d;
        float inv = 1.0f / (d + 1e-6f);
        s_pux[tid] = dx * inv;
        s_puy[tid] = dy * inv;
    }
    __syncthreads();

    // gather x[src] | x[tgt] into AT (k-major)
#pragma unroll
    for (int t4 = 0; t4 < 16; t4++) {
        int idx = tid + t4 * 256;                 // TE*64 = 4096 float4 loads
        int e = idx >> 6;
        int j = idx & 63;
        int row = (j < 32) ? s_src[e] : s_tgt[e];
        int jj = j & 31;
        float4 v = *(const float4*)&g_x[row * DD + jj * 4];
        int k = (j < 32) ? (jj * 4) : (128 + jj * 4);
        AT[(k + 0) * AT_STR + e] = v.x;
        AT[(k + 1) * AT_STR + e] = v.y;
        AT[(k + 2) * AT_STR + e] = v.z;
        AT[(k + 3) * AT_STR + e] = v.w;
    }
    __syncthreads();

    const int tx = tid & 15, ty = tid >> 4;
    const int c0 = tx * 8, r0 = ty * 4;

    // ---- GEMM1: [64,257] @ [257,128] ----
    u64 acc[4][4];
#pragma unroll
    for (int j = 0; j < 4; j++) {
        float2 bv = *(const float2*)&b1[c0 + 2 * j];
        u64 p = pack2(bv.x, bv.y);
#pragma unroll
        for (int i = 0; i < 4; i++) acc[i][j] = p;
    }

    for (int kt = 0; kt < 8; kt++) {
        __syncthreads();
#pragma unroll
        for (int t4 = 0; t4 < 4; t4++) {
            int idx = tid + t4 * 256;
            int r = idx >> 5, c4 = idx & 31;
            *(float4*)&Bs[r * 128 + c4 * 4] = *(const float4*)&W1[(kt * 32 + r) * DD + c4 * 4];
        }
        __syncthreads();
#pragma unroll
        for (int kk = 0; kk < 32; kk++) {
            float4 a = *(const float4*)&AT[(kt * 32 + kk) * AT_STR + r0];
            u64 ad[4] = {pack2(a.x, a.x), pack2(a.y, a.y), pack2(a.z, a.z), pack2(a.w, a.w)};
            const u64* bp = (const u64*)&Bs[kk * 128 + c0];
            ulonglong2 bl = *(const ulonglong2*)bp;
            ulonglong2 bh = *(const ulonglong2*)(bp + 2);
            u64 bv[4] = {bl.x, bl.y, bh.x, bh.y};
#pragma unroll
            for (int i = 0; i < 4; i++)
#pragma unroll
                for (int j = 0; j < 4; j++)
                    acc[i][j] = fma2(ad[i], bv[j], acc[i][j]);
        }
    }
    // dist column (k = 256)
    {
        u64 wv[4];
#pragma unroll
        for (int j = 0; j < 4; j++) {
            float2 w = *(const float2*)&W1[256 * DD + c0 + 2 * j];
            wv[j] = pack2(w.x, w.y);
        }
#pragma unroll
        for (int i = 0; i < 4; i++) {
            float dv = s_dist[r0 + i];
            u64 dd = pack2(dv, dv);
#pragma unroll
            for (int j = 0; j < 4; j++) acc[i][j] = fma2(dd, wv[j], acc[i][j]);
        }
    }
    __syncthreads();   // all reads of AT done

    // silu -> H_T (k-major, reuse AT)
#pragma unroll
    for (int i = 0; i < 4; i++)
#pragma unroll
        for (int j = 0; j < 4; j++) {
            float2 v = unpack2(acc[i][j]);
            AT[(c0 + 2 * j)     * AT_STR + r0 + i] = silu(v.x);
            AT[(c0 + 2 * j + 1) * AT_STR + r0 + i] = silu(v.y);
        }
    __syncthreads();

    // ---- GEMM2: [64,128] @ [128,128] ----
    u64 acc2[4][4];
#pragma unroll
    for (int j = 0; j < 4; j++) {
        float2 bv = *(const float2*)&b2[c0 + 2 * j];
        u64 p = pack2(bv.x, bv.y);
#pragma unroll
        for (int i = 0; i < 4; i++) acc2[i][j] = p;
    }
    for (int kt = 0; kt < 4; kt++) {
        __syncthreads();
#pragma unroll
        for (int t4 = 0; t4 < 4; t4++) {
            int idx = tid + t4 * 256;
            int r = idx >> 5, c4 = idx & 31;
            *(float4*)&Bs[r * 128 + c4 * 4] = *(const float4*)&W2[(kt * 32 + r) * DD + c4 * 4];
        }
        __syncthreads();
#pragma unroll
        for (int kk = 0; kk < 32; kk++) {
            float4 a = *(const float4*)&AT[(kt * 32 + kk) * AT_STR + r0];
            u64 ad[4] = {pack2(a.x, a.x), pack2(a.y, a.y), pack2(a.z, a.z), pack2(a.w, a.w)};
            const u64* bp = (const u64*)&Bs[kk * 128 + c0];
            ulonglong2 bl = *(const ulonglong2*)bp;
            ulonglong2 bh = *(const ulonglong2*)(bp + 2);
            u64 bv[4] = {bl.x, bl.y, bh.x, bh.y};
#pragma unroll
            for (int i = 0; i < 4; i++)
#pragma unroll
                for (int j = 0; j < 4; j++)
                    acc2[i][j] = fma2(ad[i], bv[j], acc2[i][j]);
        }
    }

    // unpack msg
    float m[4][8];
#pragma unroll
    for (int i = 0; i < 4; i++)
#pragma unroll
        for (int j = 0; j < 4; j++) {
            float2 v = unpack2(acc2[i][j]);
            m[i][2 * j] = v.x;
            m[i][2 * j + 1] = v.y;
        }

    __syncthreads();   // H_T reads done — safe to overwrite with M_T
#pragma unroll
    for (int i = 0; i < 4; i++)
#pragma unroll
        for (int c = 0; c < 8; c++)
            AT[(c0 + c) * AT_STR + r0 + i] = m[i][c];

    // agg atomics (float4, sm_90+)
#pragma unroll
    for (int i = 0; i < 4; i++) {
        int e = r0 + i;
        if (e0 + e < EE) {
            float* dst = &g_agg[s_tgt[e] * DD + c0];
            atomicAdd((float4*)dst, make_float4(m[i][0], m[i][1], m[i][2], m[i][3]));
            atomicAdd((float4*)(dst + 4), make_float4(m[i][4], m[i][5], m[i][6], m[i][7]));
        }
    }
    __syncthreads();

    // pw scalar MLP: 4 threads per edge reduce msg . pw1
    {
        int e = tid >> 2, sub = tid & 3;
        float s = 0.0f;
#pragma unroll
        for (int c = 0; c < 32; c++)
            s = fmaf(AT[(sub * 32 + c) * AT_STR + e], pw1[sub * 32 + c], s);
        s += __shfl_xor_sync(0xFFFFFFFFu, s, 1);
        s += __shfl_xor_sync(0xFFFFFFFFu, s, 2);
        if (sub == 0 && e0 + e < EE) {
            float z = s + s_dist[e] * pw1[128] + pb1[0];
            float h = silu(z);
            float pwv = h * pw2[0] + pb2[0];
            int t = s_tgt[e];
            atomicAdd(&g_dp[t * 2],     s_pux[e] * pwv);
            atomicAdd(&g_dp[t * 2 + 1], s_puy[e] * pwv);
        }
    }
}

// ---------------------------------------------------------------------------
// Node kernel: x += silu([x|agg] @ W1 + b1) @ W2 + b2 ;  p += dp
// ---------------------------------------------------------------------------
#define NAT (256 * AT_STR)

__global__ void __launch_bounds__(256, 2) node_kernel(
    const float* __restrict__ W1, const float* __restrict__ b1,
    const float* __restrict__ W2, const float* __restrict__ b2)
{
    extern __shared__ float sm[];
    float* AT = sm;            // [256][68], reused as H_T [128][68]
    float* Bs = sm + NAT;      // [32][128]

    const int tid = threadIdx.x;
    const int n0 = blockIdx.x * TE;

#pragma unroll
    for (int t4 = 0; t4 < 16; t4++) {
        int idx = tid + t4 * 256;
        int nl = idx >> 6;
        int j = idx & 63;
        int n = n0 + nl;
        if (n >= NN) n = 0;
        int jj = j & 31;
        const float* base = (j < 32) ? &g_x[n * DD + jj * 4] : &g_agg[n * DD + jj * 4];
        float4 v = *(const float4*)base;
        int k = (j < 32) ? (jj * 4) : (128 + jj * 4);
        AT[(k + 0) * AT_STR + nl] = v.x;
        AT[(k + 1) * AT_STR + nl] = v.y;
        AT[(k + 2) * AT_STR + nl] = v.z;
        AT[(k + 3) * AT_STR + nl] = v.w;
    }
    __syncthreads();

    const int tx = tid & 15, ty = tid >> 4;
    const int c0 = tx * 8, r0 = ty * 4;

    u64 acc[4][4];
#pragma unroll
    for (int j = 0; j < 4; j++) {
        float2 bv = *(const float2*)&b1[c0 + 2 * j];
        u64 p = pack2(bv.x, bv.y);
#pragma unroll
        for (int i = 0; i < 4; i++) acc[i][j] = p;
    }
    for (int kt = 0; kt < 8; kt++) {
        __syncthreads();
#pragma unroll
        for (int t4 = 0; t4 < 4; t4++) {
            int idx = tid + t4 * 256;
            int r = idx >> 5, c4 = idx & 31;
            *(float4*)&Bs[r * 128 + c4 * 4] = *(const float4*)&W1[(kt * 32 + r) * DD + c4 * 4];
        }
        __syncthreads();
#pragma unroll
        for (int kk = 0; kk < 32; kk++) {
            float4 a = *(const float4*)&AT[(kt * 32 + kk) * AT_STR + r0];
            u64 ad[4] = {pack2(a.x, a.x), pack2(a.y, a.y), pack2(a.z, a.z), pack2(a.w, a.w)};
            const u64* bp = (const u64*)&Bs[kk * 128 + c0];
            ulonglong2 bl = *(const ulonglong2*)bp;
            ulonglong2 bh = *(const ulonglong2*)(bp + 2);
            u64 bv[4] = {bl.x, bl.y, bh.x, bh.y};
#pragma unroll
            for (int i = 0; i < 4; i++)
#pragma unroll
                for (int j = 0; j < 4; j++)
                    acc[i][j] = fma2(ad[i], bv[j], acc[i][j]);
        }
    }
    __syncthreads();
#pragma unroll
    for (int i = 0; i < 4; i++)
#pragma unroll
        for (int j = 0; j < 4; j++) {
            float2 v = unpack2(acc[i][j]);
            AT[(c0 + 2 * j)     * AT_STR + r0 + i] = silu(v.x);
            AT[(c0 + 2 * j + 1) * AT_STR + r0 + i] = silu(v.y);
        }
    __syncthreads();

    u64 acc2[4][4];
#pragma unroll
    for (int j = 0; j < 4; j++) {
        float2 bv = *(const float2*)&b2[c0 + 2 * j];
        u64 p = pack2(bv.x, bv.y);
#pragma unroll
        for (int i = 0; i < 4; i++) acc2[i][j] = p;
    }
    for (int kt = 0; kt < 4; kt++) {
        __syncthreads();
#pragma unroll
        for (int t4 = 0; t4 < 4; t4++) {
            int idx = tid + t4 * 256;
            int r = idx >> 5, c4 = idx & 31;
            *(float4*)&Bs[r * 128 + c4 * 4] = *(const float4*)&W2[(kt * 32 + r) * DD + c4 * 4];
        }
        __syncthreads();
#pragma unroll
        for (int kk = 0; kk < 32; kk++) {
            float4 a = *(const float4*)&AT[(kt * 32 + kk) * AT_STR + r0];
            u64 ad[4] = {pack2(a.x, a.x), pack2(a.y, a.y), pack2(a.z, a.z), pack2(a.w, a.w)};
            const u64* bp = (const u64*)&Bs[kk * 128 + c0];
            ulonglong2 bl = *(const ulonglong2*)bp;
            ulonglong2 bh = *(const ulonglong2*)(bp + 2);
            u64 bv[4] = {bl.x, bl.y, bh.x, bh.y};
#pragma unroll
            for (int i = 0; i < 4; i++)
#pragma unroll
                for (int j = 0; j < 4; j++)
                    acc2[i][j] = fma2(ad[i], bv[j], acc2[i][j]);
        }
    }

    // residual update of x
#pragma unroll
    for (int i = 0; i < 4; i++) {
        int n = n0 + r0 + i;
        if (n < NN) {
            float4* xr = (float4*)&g_x[n * DD + c0];
            float4 o0 = xr[0], o1 = xr[1];
            float2 v0 = unpack2(acc2[i][0]);
            float2 v1 = unpack2(acc2[i][1]);
            float2 v2 = unpack2(acc2[i][2]);
            float2 v3 = unpack2(acc2[i][3]);
            o0.x += v0.x; o0.y += v0.y; o0.z += v1.x; o0.w += v1.y;
            o1.x += v2.x; o1.y += v2.y; o1.z += v3.x; o1.w += v3.y;
            xr[0] = o0; xr[1] = o1;
        }
    }

    // p += dp
    if (tid < TE * 2) {
        int nl = tid >> 1, comp = tid & 1;
        int n = n0 + nl;
        if (n < NN) g_p[n * 2 + comp] += g_dp[n * 2 + comp];
    }
}

// ---------------------------------------------------------------------------
// LayerNorm: warp per node
// ---------------------------------------------------------------------------
__global__ void ln_kernel(const float* __restrict__ gma, const float* __restrict__ bta,
                          float* __restrict__ out) {
    int warp = threadIdx.x >> 5, lane = threadIdx.x & 31;
    int n = blockIdx.x * 8 + warp;
    if (n >= NN) return;
    float4 v = *(const float4*)&g_x[n * DD + lane * 4];
    float s = v.x + v.y + v.z + v.w;
    float sq = v.x * v.x + v.y * v.y + v.z * v.z + v.w * v.w;
#pragma unroll
    for (int o = 16; o > 0; o >>= 1) {
        s  += __shfl_xor_sync(0xFFFFFFFFu, s, o);
        sq += __shfl_xor_sync(0xFFFFFFFFu, sq, o);
    }
    float mu = s * (1.0f / 128.0f);
    float var = sq * (1.0f / 128.0f) - mu * mu;
    float r = rsqrtf(var + 1e-5f);
    float4 g4 = *(const float4*)&gma[lane * 4];
    float4 b4 = *(const float4*)&bta[lane * 4];
    float4 o4;
    o4.x = (v.x - mu) * r * g4.x + b4.x;
    o4.y = (v.y - mu) * r * g4.y + b4.y;
    o4.z = (v.z - mu) * r * g4.z + b4.z;
    o4.w = (v.w - mu) * r * g4.w + b4.w;
    *(float4*)&out[n * DD + lane * 4] = o4;
}

// ---------------------------------------------------------------------------
extern "C" void kernel_launch(void* const* d_in, const int* in_sizes, int n_in,
                              void* d_out, int out_size) {
    (void)in_sizes; (void)n_in; (void)out_size;
    const float* nf   = (const float*)d_in[0];
    const float* pos  = (const float*)d_in[1];
    // d_in[2] edge_attr_raw, d_in[5..6] edge_proj_*: mathematically dead
    const float* npw  = (const float*)d_in[3];
    const float* npb  = (const float*)d_in[4];
    const float* ew1  = (const float*)d_in[7];
    const float* eb1  = (const float*)d_in[8];
    const float* ew2  = (const float*)d_in[9];
    const float* eb2  = (const float*)d_in[10];
    const float* nw1  = (const float*)d_in[11];
    const float* nb1  = (const float*)d_in[12];
    const float* nw2  = (const float*)d_in[13];
    const float* nb2  = (const float*)d_in[14];
    const float* pw1  = (const float*)d_in[15];
    const float* pb1  = (const float*)d_in[16];
    const float* pw2  = (const float*)d_in[17];
    const float* pb2  = (const float*)d_in[18];
    const float* lng  = (const float*)d_in[19];
    const float* lnb  = (const float*)d_in[20];
    const int*   eidx = (const int*)d_in[21];

    void* agg_ptr = nullptr;
    void* dp_ptr = nullptr;
    cudaGetSymbolAddress(&agg_ptr, g_agg);
    cudaGetSymbolAddress(&dp_ptr, g_dp);

    const size_t esm = (size_t)(SM_AT + SM_BS + 3 * TE) * sizeof(float) + 2 * TE * sizeof(int);
    const size_t nsm = (size_t)(NAT + SM_BS) * sizeof(float);
    cudaFuncSetAttribute(edge_kernel, cudaFuncAttributeMaxDynamicSharedMemorySize, (int)esm);
    cudaFuncSetAttribute(node_kernel, cudaFuncAttributeMaxDynamicSharedMemorySize, (int)nsm);

    init_kernel<<<NN, DD>>>(nf, pos, npw, npb);

    for (int l = 0; l < LL; l++) {
        cudaMemsetAsync(agg_ptr, 0, (size_t)NN * DD * sizeof(float));
        cudaMemsetAsync(dp_ptr, 0, (size_t)NN * 2 * sizeof(float));
        edge_kernel<<<(EE + TE - 1) / TE, 256, esm>>>(
            ew1 + (size_t)l * 257 * 128, eb1 + l * 128,
            ew2 + (size_t)l * 128 * 128, eb2 + l * 128,
            pw1 + l * 129, pb1 + l, pw2 + l, pb2 + l, eidx);
        node_kernel<<<(NN + TE - 1) / TE, 256, nsm>>>(
            nw1 + (size_t)l * 256 * 128, nb1 + l * 128,
            nw2 + (size_t)l * 128 * 128, nb2 + l * 128);
    }

    ln_kernel<<<(NN + 7) / 8, 256>>>(lng, lnb, (float*)d_out);
}

// round 2
// speedup vs baseline: 1.5933x; 1.5933x over previous
#include <cuda_runtime.h>
#include <math.h>

#define NN 50000
#define EE 250000
#define DD 128
#define FF 12
#define LL 4
#define TE 64
#define STR 64

// Persistent scratch (no allocations allowed)
__device__ float g_x[NN * DD];
__device__ float g_p[NN * 2];
__device__ float g_agg[NN * DD];
__device__ float g_dp[NN * 2];

typedef unsigned long long u64;

__device__ __forceinline__ float silu(float z) {
    return z / (1.0f + __expf(-z));
}
__device__ __forceinline__ u64 pack2(float lo, float hi) {
    u64 r;
    asm("mov.b64 %0, {%1, %2};" : "=l"(r) : "f"(lo), "f"(hi));
    return r;
}
__device__ __forceinline__ u64 fma2(u64 a, u64 b, u64 c) {
    u64 d;
    asm("fma.rn.f32x2 %0, %1, %2, %3;" : "=l"(d) : "l"(a), "l"(b), "l"(c));
    return d;
}
__device__ __forceinline__ float2 unpack2(u64 v) {
    float2 r;
    asm("mov.b64 {%0, %1}, %2;" : "=f"(r.x), "=f"(r.y) : "l"(v));
    return r;
}

// ---------------------------------------------------------------------------
__global__ void init_kernel(const float* __restrict__ nf, const float* __restrict__ pos,
                            const float* __restrict__ Wp, const float* __restrict__ bp) {
    int n = blockIdx.x;
    int d = threadIdx.x;
    __shared__ float s_nf[FF];
    if (d < FF) s_nf[d] = nf[n * FF + d];
    __syncthreads();
    float acc = bp[d];
#pragma unroll
    for (int f = 0; f < FF; f++) acc = fmaf(s_nf[f], Wp[f * DD + d], acc);
    g_x[n * DD + d] = acc;
    if (d < 2) g_p[n * 2 + d] = pos[n * 2 + d];
}

// ---------------------------------------------------------------------------
// Shared GEMM micro-kernel pieces
//   AT: k-major A tile [Kmax][STR] with XOR swizzle on the row(e) index
//   Bs: staged B tile [32][128]
//   thread tile: 8 rows (r0=ty*8) x 8 cols (c0=tx*8), 128 threads
// ---------------------------------------------------------------------------
#define SM_AT (256 * STR)
#define SM_BS (32 * DD)

#define GEMM_TILE(kt, AT, Bs, acc)                                              \
    {                                                                           \
        _Pragma("unroll")                                                       \
        for (int k8 = 0; k8 < 4; k8++) {                                        \
            const int kbase = (kt) * 32 + k8 * 8;                               \
            const int rs = r0 ^ ((((kbase) >> 3) & 7) << 3);                    \
            _Pragma("unroll")                                                   \
            for (int k2 = 0; k2 < 8; k2++) {                                    \
                const int k = kbase + k2;                                       \
                const float* arow = &(AT)[k * STR + rs];                        \
                float4 a0 = *(const float4*)arow;                               \
                float4 a1 = *(const float4*)(arow + 4);                         \
                u64 ad[8] = {pack2(a0.x, a0.x), pack2(a0.y, a0.y),              \
                             pack2(a0.z, a0.z), pack2(a0.w, a0.w),              \
                             pack2(a1.x, a1.x), pack2(a1.y, a1.y),              \
                             pack2(a1.z, a1.z), pack2(a1.w, a1.w)};             \
                const u64* bp_ = (const u64*)&(Bs)[(k8 * 8 + k2) * DD + c0];    \
                u64 bv[4] = {bp_[0], bp_[1], bp_[2], bp_[3]};                   \
                _Pragma("unroll")                                               \
                for (int i = 0; i < 8; i++)                                     \
                    _Pragma("unroll")                                           \
                    for (int j = 0; j < 4; j++)                                 \
                        acc[i][j] = fma2(ad[i], bv[j], acc[i][j]);              \
            }                                                                   \
        }                                                                       \
    }

#define STAGE_B(W, kt, Bs)                                                      \
    {                                                                           \
        _Pragma("unroll")                                                       \
        for (int t = 0; t < 8; t++) {                                           \
            int idx = t * 128 + tid;                                            \
            int r = idx >> 5, c4 = idx & 31;                                    \
            *(float4*)&(Bs)[r * DD + c4 * 4] =                                  \
                *(const float4*)&(W)[(kt * 32 + r) * DD + c4 * 4];              \
        }                                                                       \
    }

// ---------------------------------------------------------------------------
// Edge kernel
// ---------------------------------------------------------------------------
__global__ void __launch_bounds__(128, 2) edge_kernel(
    const float* __restrict__ W1, const float* __restrict__ b1,
    const float* __restrict__ W2, const float* __restrict__ b2,
    const float* __restrict__ pw1, const float* __restrict__ pb1,
    const float* __restrict__ pw2, const float* __restrict__ pb2,
    const int* __restrict__ eidx)
{
    extern __shared__ float sm[];
    float* AT = sm;                    // [256][64], reused for H_T [128][64]
    float* Bs = sm + SM_AT;            // [32][128]
    float* s_dist = Bs + SM_BS;        // [64]
    float* s_pux = s_dist + TE;
    float* s_puy = s_pux + TE;
    int* s_src = (int*)(s_puy + TE);
    int* s_tgt = s_src + TE;

    const int tid = threadIdx.x;
    const int e0 = blockIdx.x * TE;

    if (tid < TE) {
        int ge = e0 + tid;
        int src = 0, tgt = 0;
        if (ge < EE) { src = eidx[ge]; tgt = eidx[EE + ge]; }
        s_src[tid] = src;
        s_tgt[tid] = tgt;
        float2 ps = *(const float2*)&g_p[src * 2];
        float2 pt = *(const float2*)&g_p[tgt * 2];
        float dx = pt.x - ps.x, dy = pt.y - ps.y;
        float d = sqrtf(dx * dx + dy * dy);
        s_dist[tid] = d;
        float inv = 1.0f / (d + 1e-6f);
        s_pux[tid] = dx * inv;
        s_puy[tid] = dy * inv;
    }
    __syncthreads();

    // gather x[src] | x[tgt] into AT (k-major, swizzled, conflict-free STS)
#pragma unroll
    for (int t = 0; t < 32; t++) {
        int idx = t * 128 + tid;
        int e = idx & 63;
        int j = idx >> 6;
        int jj = j & 31;
        int row = (j < 32) ? s_src[e] : s_tgt[e];
        float4 v = *(const float4*)&g_x[(size_t)row * DD + jj * 4];
        int kb = (j < 32) ? (jj * 4) : (DD + jj * 4);
        int es = e ^ (((kb >> 3) & 7) << 3);
        float* dst = &AT[kb * STR + es];
        dst[0 * STR] = v.x;
        dst[1 * STR] = v.y;
        dst[2 * STR] = v.z;
        dst[3 * STR] = v.w;
    }

    const int tx = tid & 15, ty = tid >> 4;
    const int c0 = tx * 8, r0 = ty * 8;

    // ---- GEMM1: [64,257] @ [257,128] ----
    u64 acc[8][4];
    {
        u64 bb[4];
#pragma unroll
        for (int j = 0; j < 4; j++) {
            float2 bv = *(const float2*)&b1[c0 + 2 * j];
            bb[j] = pack2(bv.x, bv.y);
        }
#pragma unroll
        for (int i = 0; i < 8; i++)
#pragma unroll
            for (int j = 0; j < 4; j++) acc[i][j] = bb[j];
    }

    for (int kt = 0; kt < 8; kt++) {
        __syncthreads();
        STAGE_B(W1, kt, Bs);
        __syncthreads();
        GEMM_TILE(kt, AT, Bs, acc);
    }
    // dist column (k = 256)
    {
        u64 wv[4];
#pragma unroll
        for (int j = 0; j < 4; j++) {
            float2 w = *(const float2*)&W1[256 * DD + c0 + 2 * j];
            wv[j] = pack2(w.x, w.y);
        }
#pragma unroll
        for (int i = 0; i < 8; i++) {
            float dv = s_dist[r0 + i];
            u64 dd = pack2(dv, dv);
#pragma unroll
            for (int j = 0; j < 4; j++) acc[i][j] = fma2(dd, wv[j], acc[i][j]);
        }
    }
    __syncthreads();   // all reads of AT done

    // silu -> H_T (k-major, swizzled, float4 along rows)
#pragma unroll
    for (int c2 = 0; c2 < 4; c2++) {
        float h0[8], h1[8];
#pragma unroll
        for (int i = 0; i < 8; i++) {
            float2 v = unpack2(acc[i][c2]);
            h0[i] = silu(v.x);
            h1[i] = silu(v.y);
        }
#pragma unroll
        for (int s = 0; s < 2; s++) {
            const float* h = s ? h1 : h0;
            int kcol = c0 + 2 * c2 + s;
            int rs = r0 ^ (((kcol >> 3) & 7) << 3);
            *(float4*)&AT[kcol * STR + rs]     = make_float4(h[0], h[1], h[2], h[3]);
            *(float4*)&AT[kcol * STR + rs + 4] = make_float4(h[4], h[5], h[6], h[7]);
        }
    }

    // ---- GEMM2: [64,128] @ [128,128] ----
    u64 acc2[8][4];
    {
        u64 bb[4];
#pragma unroll
        for (int j = 0; j < 4; j++) {
            float2 bv = *(const float2*)&b2[c0 + 2 * j];
            bb[j] = pack2(bv.x, bv.y);
        }
#pragma unroll
        for (int i = 0; i < 8; i++)
#pragma unroll
            for (int j = 0; j < 4; j++) acc2[i][j] = bb[j];
    }
    for (int kt = 0; kt < 4; kt++) {
        __syncthreads();
        STAGE_B(W2, kt, Bs);
        __syncthreads();
        GEMM_TILE(kt, AT, Bs, acc2);
    }

    // unpack msg
    float m[8][8];
#pragma unroll
    for (int i = 0; i < 8; i++)
#pragma unroll
        for (int j = 0; j < 4; j++) {
            float2 v = unpack2(acc2[i][j]);
            m[i][2 * j] = v.x;
            m[i][2 * j + 1] = v.y;
        }

    // agg atomics straight from registers
#pragma unroll
    for (int i = 0; i < 8; i++) {
        int e = r0 + i;
        if (e0 + e < EE) {
            float* dst = &g_agg[(size_t)s_tgt[e] * DD + c0];
            atomicAdd((float4*)dst, make_float4(m[i][0], m[i][1], m[i][2], m[i][3]));
            atomicAdd((float4*)(dst + 4), make_float4(m[i][4], m[i][5], m[i][6], m[i][7]));
        }
    }

    // pw MLP: per-row dot(msg, pw1[0:128]) via register partials + shfl reduce
    {
        float w8[8];
#pragma unroll
        for (int c = 0; c < 8; c++) w8[c] = __ldg(&pw1[c0 + c]);
        float dot[8];
#pragma unroll
        for (int i = 0; i < 8; i++) {
            float s = m[i][0] * w8[0];
#pragma unroll
            for (int c = 1; c < 8; c++) s = fmaf(m[i][c], w8[c], s);
            dot[i] = s;
        }
#pragma unroll
        for (int off = 1; off < 16; off <<= 1)
#pragma unroll
            for (int i = 0; i < 8; i++)
                dot[i] += __shfl_xor_sync(0xFFFFFFFFu, dot[i], off);
        if (tx == 0) {
            float w_d  = __ldg(&pw1[128]);
            float pb1v = __ldg(pb1);
            float pw2v = __ldg(pw2);
            float pb2v = __ldg(pb2);
#pragma unroll
            for (int i = 0; i < 8; i++) {
                int e = r0 + i;
                if (e0 + e < EE) {
                    float z = dot[i] + s_dist[e] * w_d + pb1v;
                    float pwv = silu(z) * pw2v + pb2v;
                    int tg = s_tgt[e];
                    atomicAdd(&g_dp[tg * 2],     s_pux[e] * pwv);
                    atomicAdd(&g_dp[tg * 2 + 1], s_puy[e] * pwv);
                }
            }
        }
    }
}

// ---------------------------------------------------------------------------
// Node kernel: x += silu([x|agg] @ W1 + b1) @ W2 + b2 ;  p += dp
// ---------------------------------------------------------------------------
__global__ void __launch_bounds__(128, 2) node_kernel(
    const float* __restrict__ W1, const float* __restrict__ b1,
    const float* __restrict__ W2, const float* __restrict__ b2)
{
    extern __shared__ float sm[];
    float* AT = sm;            // [256][64], reused as H_T [128][64]
    float* Bs = sm + SM_AT;    // [32][128]

    const int tid = threadIdx.x;
    const int n0 = blockIdx.x * TE;

#pragma unroll
    for (int t = 0; t < 32; t++) {
        int idx = t * 128 + tid;
        int e = idx & 63;
        int j = idx >> 6;
        int jj = j & 31;
        int n = n0 + e;
        if (n >= NN) n = 0;
        const float* base = (j < 32) ? &g_x[(size_t)n * DD + jj * 4]
                                     : &g_agg[(size_t)n * DD + jj * 4];
        float4 v = *(const float4*)base;
        int kb = (j < 32) ? (jj * 4) : (DD + jj * 4);
        int es = e ^ (((kb >> 3) & 7) << 3);
        float* dst = &AT[kb * STR + es];
        dst[0 * STR] = v.x;
        dst[1 * STR] = v.y;
        dst[2 * STR] = v.z;
        dst[3 * STR] = v.w;
    }

    const int tx = tid & 15, ty = tid >> 4;
    const int c0 = tx * 8, r0 = ty * 8;

    u64 acc[8][4];
    {
        u64 bb[4];
#pragma unroll
        for (int j = 0; j < 4; j++) {
            float2 bv = *(const float2*)&b1[c0 + 2 * j];
            bb[j] = pack2(bv.x, bv.y);
        }
#pragma unroll
        for (int i = 0; i < 8; i++)
#pragma unroll
            for (int j = 0; j < 4; j++) acc[i][j] = bb[j];
    }
    for (int kt = 0; kt < 8; kt++) {
        __syncthreads();
        STAGE_B(W1, kt, Bs);
        __syncthreads();
        GEMM_TILE(kt, AT, Bs, acc);
    }
    __syncthreads();

#pragma unroll
    for (int c2 = 0; c2 < 4; c2++) {
        float h0[8], h1[8];
#pragma unroll
        for (int i = 0; i < 8; i++) {
            float2 v = unpack2(acc[i][c2]);
            h0[i] = silu(v.x);
            h1[i] = silu(v.y);
        }
#pragma unroll
        for (int s = 0; s < 2; s++) {
            const float* h = s ? h1 : h0;
            int kcol = c0 + 2 * c2 + s;
            int rs = r0 ^ (((kcol >> 3) & 7) << 3);
            *(float4*)&AT[kcol * STR + rs]     = make_float4(h[0], h[1], h[2], h[3]);
            *(float4*)&AT[kcol * STR + rs + 4] = make_float4(h[4], h[5], h[6], h[7]);
        }
    }

    u64 acc2[8][4];
    {
        u64 bb[4];
#pragma unroll
        for (int j = 0; j < 4; j++) {
            float2 bv = *(const float2*)&b2[c0 + 2 * j];
            bb[j] = pack2(bv.x, bv.y);
        }
#pragma unroll
        for (int i = 0; i < 8; i++)
#pragma unroll
            for (int j = 0; j < 4; j++) acc2[i][j] = bb[j];
    }
    for (int kt = 0; kt < 4; kt++) {
        __syncthreads();
        STAGE_B(W2, kt, Bs);
        __syncthreads();
        GEMM_TILE(kt, AT, Bs, acc2);
    }

    // residual update of x
#pragma unroll
    for (int i = 0; i < 8; i++) {
        int n = n0 + r0 + i;
        if (n < NN) {
            float4* xr = (float4*)&g_x[(size_t)n * DD + c0];
            float4 o0 = xr[0], o1 = xr[1];
            float2 v0 = unpack2(acc2[i][0]);
            float2 v1 = unpack2(acc2[i][1]);
            float2 v2 = unpack2(acc2[i][2]);
            float2 v3 = unpack2(acc2[i][3]);
            o0.x += v0.x; o0.y += v0.y; o0.z += v1.x; o0.w += v1.y;
            o1.x += v2.x; o1.y += v2.y; o1.z += v3.x; o1.w += v3.y;
            xr[0] = o0; xr[1] = o1;
        }
    }

    // p += dp  (128 threads cover 64 nodes x 2 components)
    {
        int nl = tid >> 1, comp = tid & 1;
        int n = n0 + nl;
        if (n < NN) g_p[n * 2 + comp] += g_dp[n * 2 + comp];
    }
}

// ---------------------------------------------------------------------------
// LayerNorm: warp per node
// ---------------------------------------------------------------------------
__global__ void ln_kernel(const float* __restrict__ gma, const float* __restrict__ bta,
                          float* __restrict__ out) {
    int warp = threadIdx.x >> 5, lane = threadIdx.x & 31;
    int n = blockIdx.x * 8 + warp;
    if (n >= NN) return;
    float4 v = *(const float4*)&g_x[(size_t)n * DD + lane * 4];
    float s = v.x + v.y + v.z + v.w;
    float sq = v.x * v.x + v.y * v.y + v.z * v.z + v.w * v.w;
#pragma unroll
    for (int o = 16; o > 0; o >>= 1) {
        s  += __shfl_xor_sync(0xFFFFFFFFu, s, o);
        sq += __shfl_xor_sync(0xFFFFFFFFu, sq, o);
    }
    float mu = s * (1.0f / 128.0f);
    float var = sq * (1.0f / 128.0f) - mu * mu;
    float r = rsqrtf(var + 1e-5f);
    float4 g4 = *(const float4*)&gma[lane * 4];
    float4 b4 = *(const float4*)&bta[lane * 4];
    float4 o4;
    o4.x = (v.x - mu) * r * g4.x + b4.x;
    o4.y = (v.y - mu) * r * g4.y + b4.y;
    o4.z = (v.z - mu) * r * g4.z + b4.z;
    o4.w = (v.w - mu) * r * g4.w + b4.w;
    *(float4*)&out[(size_t)n * DD + lane * 4] = o4;
}

// ---------------------------------------------------------------------------
extern "C" void kernel_launch(void* const* d_in, const int* in_sizes, int n_in,
                              void* d_out, int out_size) {
    (void)in_sizes; (void)n_in; (void)out_size;
    const float* nf   = (const float*)d_in[0];
    const float* pos  = (const float*)d_in[1];
    const float* npw  = (const float*)d_in[3];
    const float* npb  = (const float*)d_in[4];
    const float* ew1  = (const float*)d_in[7];
    const float* eb1  = (const float*)d_in[8];
    const float* ew2  = (const float*)d_in[9];
    const float* eb2  = (const float*)d_in[10];
    const float* nw1  = (const float*)d_in[11];
    const float* nb1  = (const float*)d_in[12];
    const float* nw2  = (const float*)d_in[13];
    const float* nb2  = (const float*)d_in[14];
    const float* pw1  = (const float*)d_in[15];
    const float* pb1  = (const float*)d_in[16];
    const float* pw2  = (const float*)d_in[17];
    const float* pb2  = (const float*)d_in[18];
    const float* lng  = (const float*)d_in[19];
    const float* lnb  = (const float*)d_in[20];
    const int*   eidx = (const int*)d_in[21];

    void* agg_ptr = nullptr;
    void* dp_ptr = nullptr;
    cudaGetSymbolAddress(&agg_ptr, g_agg);
    cudaGetSymbolAddress(&dp_ptr, g_dp);

    const size_t esm = (size_t)(SM_AT + SM_BS + 3 * TE) * sizeof(float) + 2 * TE * sizeof(int);
    const size_t nsm = (size_t)(SM_AT + SM_BS) * sizeof(float);
    cudaFuncSetAttribute(edge_kernel, cudaFuncAttributeMaxDynamicSharedMemorySize, (int)esm);
    cudaFuncSetAttribute(node_kernel, cudaFuncAttributeMaxDynamicSharedMemorySize, (int)nsm);

    init_kernel<<<NN, DD>>>(nf, pos, npw, npb);

    for (int l = 0; l < LL; l++) {
        cudaMemsetAsync(agg_ptr, 0, (size_t)NN * DD * sizeof(float));
        cudaMemsetAsync(dp_ptr, 0, (size_t)NN * 2 * sizeof(float));
        edge_kernel<<<(EE + TE - 1) / TE, 128, esm>>>(
            ew1 + (size_t)l * 257 * 128, eb1 + l * 128,
            ew2 + (size_t)l * 128 * 128, eb2 + l * 128,
            pw1 + l * 129, pb1 + l, pw2 + l, pb2 + l, eidx);
        node_kernel<<<(NN + TE - 1) / TE, 128, nsm>>>(
            nw1 + (size_t)l * 256 * 128, nb1 + l * 128,
            nw2 + (size_t)l * 128 * 128, nb2 + l * 128);
    }

    ln_kernel<<<(NN + 7) / 8, 256>>>(lng, lnb, (float*)d_out);
}

// round 4
// speedup vs baseline: 2.7643x; 1.7349x over previous
#include <cuda_runtime.h>
#include <cuda_bf16.h>
#include <math.h>
#include <stdint.h>

#define NN 50000
#define EE 250000
#define DD 128
#define FF 12
#define LL 4

// Persistent scratch (no allocations allowed)
__device__ float g_x[NN * DD];
__device__ float g_p[NN * 2];
__device__ float g_agg[NN * DD];
__device__ float g_dp[NN * 2];
// Packed bf16x2 split weights, per layer 98304 words:
//   eW1 @0 (4 chunks x 8192), eW2 @32768 (2), nW1 @49152 (4), nW2 @81920 (2)
// chunk layout: [n(128)][hi 32 words | lo 32 words]
__device__ uint32_t g_wt[LL * 98304];

__device__ __forceinline__ float silu(float z) {
    return z / (1.0f + __expf(-z));
}

// split a pair of floats into packed bf16x2 hi word + lo word
__device__ __forceinline__ void split_pair(float v0, float v1, uint32_t& hw, uint32_t& lw) {
    __nv_bfloat162 h2 = __floats2bfloat162_rn(v0, v1);
    float2 hf = __bfloat1622float2(h2);
    __nv_bfloat162 l2 = __floats2bfloat162_rn(v0 - hf.x, v1 - hf.y);
    hw = *(uint32_t*)&h2;
    lw = *(uint32_t*)&l2;
}

#define MMA(c, a, b0, b1)                                                       \
    asm volatile(                                                               \
        "mma.sync.aligned.m16n8k16.row.col.f32.bf16.bf16.f32 "                  \
        "{%0,%1,%2,%3}, {%4,%5,%6,%7}, {%8,%9}, {%0,%1,%2,%3};"                 \
        : "+f"((c)[0]), "+f"((c)[1]), "+f"((c)[2]), "+f"((c)[3])                \
        : "r"((a)[0]), "r"((a)[1]), "r"((a)[2]), "r"((a)[3]), "r"(b0), "r"(b1))

// ---------------------------------------------------------------------------
// SMEM word layout (uint32 words)
//   H region:   [0 .. 17408)  (2 chunks x 8704); GEMM1 A-chunk lives at [0..8704)
//   B stage:    [17408 .. 26112)
//   meta:       [26112 .. 27528)
// ---------------------------------------------------------------------------
#define W_H    0
#define W_AS   0
#define W_BS   17408
#define W_META 26112
#define SMEM_WORDS (W_META + 1416)
#define SMEM_BYTES (SMEM_WORDS * 4)

// meta float offsets (relative to W_META)
#define M_DIST 0
#define M_PUX  128
#define M_PUY  256
#define M_B1   384
#define M_W256 512
#define M_B2   640
#define M_PW1  768     // 129 floats
#define M_DOTA 900
#define M_DOTB 1028
#define M_SRC  1160    // int
#define M_TGT  1288    // int

// ---------------------------------------------------------------------------
// Weight prep: W [K][128] f32 -> per-chunk packed split layout
// ---------------------------------------------------------------------------
__global__ void prep_w(const float* __restrict__ W, uint32_t* __restrict__ out) {
    int c = blockIdx.x;
    int tid = threadIdx.x;
#pragma unroll
    for (int q = 0; q < 16; q++) {
        int idx = q * 256 + tid;          // 4096 = 128 n x 32 kw
        int n = idx >> 5, kw = idx & 31;
        float v0 = W[(size_t)(c * 64 + 2 * kw) * DD + n];
        float v1 = W[(size_t)(c * 64 + 2 * kw + 1) * DD + n];
        uint32_t hw, lw;
        split_pair(v0, v1, hw, lw);
        out[(size_t)c * 8192 + n * 64 + kw] = hw;
        out[(size_t)c * 8192 + n * 64 + 32 + kw] = lw;
    }
}

// ---------------------------------------------------------------------------
__global__ void init_kernel(const float* __restrict__ nf, const float* __restrict__ pos,
                            const float* __restrict__ Wp, const float* __restrict__ bp) {
    int n = blockIdx.x;
    int d = threadIdx.x;
    __shared__ float s_nf[FF];
    if (d < FF) s_nf[d] = nf[n * FF + d];
    __syncthreads();
    float acc = bp[d];
#pragma unroll
    for (int f = 0; f < FF; f++) acc = fmaf(s_nf[f], Wp[f * DD + d], acc);
    g_x[n * DD + d] = acc;
    if (d < 2) g_p[n * 2 + d] = pos[n * 2 + d];
}

// ---------------------------------------------------------------------------
// Copy one B chunk [128][64 words] global -> smem [128][68]
// ---------------------------------------------------------------------------
__device__ __forceinline__ void copy_b(uint32_t* Bs, const uint32_t* __restrict__ gw, int tid) {
#pragma unroll
    for (int q = 0; q < 8; q++) {
        int i = q * 256 + tid;            // 2048 uint4
        int n = i >> 4, w4 = i & 15;
        *(uint4*)(Bs + n * 68 + w4 * 4) = ((const uint4*)gw)[i];
    }
}

// ---------------------------------------------------------------------------
// One K=64 chunk of MMAs, 3 split passes. Warp tile 32x64.
// ---------------------------------------------------------------------------
__device__ __forceinline__ void mma_chunk(const uint32_t* __restrict__ As,
                                          const uint32_t* __restrict__ Bs,
                                          float acc[2][8][4],
                                          int m0w, int n0w, int g, int t) {
    for (int pass = 0; pass < 3; pass++) {
        const int aS = (pass == 1) ? 32 : 0;
        const int bS = (pass == 2) ? 32 : 0;
#pragma unroll
        for (int ks = 0; ks < 4; ks++) {
            const int kw = ks * 8 + t;
            uint32_t a[2][4];
#pragma unroll
            for (int mt = 0; mt < 2; mt++) {
                const uint32_t* ap = As + (m0w + mt * 16 + g) * 68 + aS + kw;
                a[mt][0] = ap[0];
                a[mt][1] = ap[8 * 68];
                a[mt][2] = ap[4];
                a[mt][3] = ap[8 * 68 + 4];
            }
#pragma unroll
            for (int nt = 0; nt < 8; nt++) {
                const uint32_t* bp = Bs + (n0w + nt * 8 + g) * 68 + bS + kw;
                uint32_t b0 = bp[0], b1 = bp[4];
                MMA(acc[0][nt], a[0], b0, b1);
                MMA(acc[1][nt], a[1], b0, b1);
            }
        }
    }
}

// ---------------------------------------------------------------------------
// Layer kernel (EDGE: 128 edges/block; NODE: 128 nodes/block), 256 threads
// ---------------------------------------------------------------------------
template <bool EDGE>
__global__ void __launch_bounds__(256, 2) layer_kernel(
    const uint32_t* __restrict__ wB1, const uint32_t* __restrict__ wB2,
    const float* __restrict__ ew1_last,   // ew1 + 256*128 (edge only)
    const float* __restrict__ b1, const float* __restrict__ b2,
    const float* __restrict__ pw1, const float* __restrict__ pb1,
    const float* __restrict__ pw2, const float* __restrict__ pb2,
    const int* __restrict__ eidx)
{
    extern __shared__ uint32_t SH[];
    float* mp = (float*)(SH + W_META);
    int* s_src = (int*)(mp + M_SRC);
    int* s_tgt = (int*)(mp + M_TGT);

    const int tid = threadIdx.x;
    const int lane = tid & 31, w = tid >> 5;
    const int g = lane >> 2, t = lane & 3;
    const int m0w = (w & 3) * 32;
    const int n0w = (w >> 2) * 64;
    const int tile0 = blockIdx.x * 128;

    // preamble
    if (tid < 128) {
        mp[M_B1 + tid] = b1[tid];
        mp[M_B2 + tid] = b2[tid];
        if (EDGE) {
            int ge = tile0 + tid;
            int s = 0, tg = 0;
            if (ge < EE) { s = eidx[ge]; tg = eidx[EE + ge]; }
            s_src[tid] = s;
            s_tgt[tid] = tg;
            float2 ps = *(const float2*)&g_p[s * 2];
            float2 pt = *(const float2*)&g_p[tg * 2];
            float dx = pt.x - ps.x, dy = pt.y - ps.y;
            float d = sqrtf(dx * dx + dy * dy);
            mp[M_DIST + tid] = d;
            float inv = 1.0f / (d + 1e-6f);
            mp[M_PUX + tid] = dx * inv;
            mp[M_PUY + tid] = dy * inv;
            mp[M_W256 + tid] = ew1_last[tid];
            mp[M_PW1 + tid] = pw1[tid];
            if (tid == 0) mp[M_PW1 + 128] = pw1[128];
        }
    }

    float acc[2][8][4];
#pragma unroll
    for (int i = 0; i < 2; i++)
#pragma unroll
        for (int j = 0; j < 8; j++)
#pragma unroll
            for (int k = 0; k < 4; k++) acc[i][j][k] = 0.0f;

    // ---- GEMM1: K = 256 in 4 chunks ----
    const int row = tid >> 1, half = tid & 1;
    for (int c = 0; c < 4; c++) {
        __syncthreads();
        {
            const float* p;
            int coloff = (c & 1) * 64 + half * 32;
            if (EDGE) {
                int node = (c < 2) ? s_src[row] : s_tgt[row];
                p = &g_x[(size_t)node * DD + coloff];
            } else {
                int nd = tile0 + row;
                if (nd >= NN) nd = NN - 1;
                const float* base = (c < 2) ? g_x : g_agg;
                p = &base[(size_t)nd * DD + coloff];
            }
            uint32_t* arow = SH + W_AS + row * 68 + half * 16;
#pragma unroll
            for (int q = 0; q < 8; q++) {
                float4 v = ((const float4*)p)[q];
                uint32_t h0, l0, h1, l1;
                split_pair(v.x, v.y, h0, l0);
                split_pair(v.z, v.w, h1, l1);
                arow[q * 2] = h0;
                arow[q * 2 + 1] = h1;
                arow[32 + q * 2] = l0;
                arow[32 + q * 2 + 1] = l1;
            }
        }
        copy_b(SH + W_BS, wB1 + (size_t)c * 8192, tid);
        __syncthreads();
        mma_chunk(SH + W_AS, SH + W_BS, acc, m0w, n0w, g, t);
    }

    // ---- Epilogue 1: bias (+dist col) -> silu -> split -> H ----
    __syncthreads();
    {
        const int hc = n0w >> 6;
        uint32_t* Hb = SH + W_H + hc * 8704;
#pragma unroll
        for (int mt = 0; mt < 2; mt++) {
            int rA = m0w + mt * 16 + g;
            int rB = rA + 8;
            float dA = EDGE ? mp[M_DIST + rA] : 0.0f;
            float dB = EDGE ? mp[M_DIST + rB] : 0.0f;
#pragma unroll
            for (int nt = 0; nt < 8; nt++) {
                int col = n0w + nt * 8 + 2 * t;
                int kw = nt * 4 + t;
                float b1a = mp[M_B1 + col], b1b = mp[M_B1 + col + 1];
                float wa = EDGE ? mp[M_W256 + col] : 0.0f;
                float wb = EDGE ? mp[M_W256 + col + 1] : 0.0f;
                float h0 = silu(acc[mt][nt][0] + b1a + dA * wa);
                float h1 = silu(acc[mt][nt][1] + b1b + dA * wb);
                float h2 = silu(acc[mt][nt][2] + b1a + dB * wa);
                float h3 = silu(acc[mt][nt][3] + b1b + dB * wb);
                uint32_t hw, lw;
                split_pair(h0, h1, hw, lw);
                Hb[rA * 68 + kw] = hw;
                Hb[rA * 68 + 32 + kw] = lw;
                split_pair(h2, h3, hw, lw);
                Hb[rB * 68 + kw] = hw;
                Hb[rB * 68 + 32 + kw] = lw;
#pragma unroll
                for (int k = 0; k < 4; k++) acc[mt][nt][k] = 0.0f;
            }
        }
    }

    // ---- GEMM2: K = 128 in 2 chunks (A = H) ----
    for (int c = 0; c < 2; c++) {
        __syncthreads();
        copy_b(SH + W_BS, wB2 + (size_t)c * 8192, tid);
        __syncthreads();
        mma_chunk(SH + W_H + c * 8704, SH + W_BS, acc, m0w, n0w, g, t);
    }

    // ---- Epilogue 2 ----
    __syncthreads();
    if (EDGE) {
        float* MS = (float*)(SH + W_H);   // msg_sm [128][132]
        const int wn = n0w >> 6;
        float dots[4] = {0, 0, 0, 0};
#pragma unroll
        for (int mt = 0; mt < 2; mt++) {
            int rA = m0w + mt * 16 + g;
            int rB = rA + 8;
#pragma unroll
            for (int nt = 0; nt < 8; nt++) {
                int col = n0w + nt * 8 + 2 * t;
                float b2a = mp[M_B2 + col], b2b = mp[M_B2 + col + 1];
                float w0 = mp[M_PW1 + col], w1 = mp[M_PW1 + col + 1];
                float ma0 = acc[mt][nt][0] + b2a;
                float ma1 = acc[mt][nt][1] + b2b;
                float mb0 = acc[mt][nt][2] + b2a;
                float mb1 = acc[mt][nt][3] + b2b;
                *(float2*)&MS[rA * 132 + col] = make_float2(ma0, ma1);
                *(float2*)&MS[rB * 132 + col] = make_float2(mb0, mb1);
                dots[mt * 2]     = fmaf(ma0, w0, fmaf(ma1, w1, dots[mt * 2]));
                dots[mt * 2 + 1] = fmaf(mb0, w0, fmaf(mb1, w1, dots[mt * 2 + 1]));
            }
        }
#pragma unroll
        for (int i = 0; i < 4; i++) {
            dots[i] += __shfl_xor_sync(0xFFFFFFFFu, dots[i], 1);
            dots[i] += __shfl_xor_sync(0xFFFFFFFFu, dots[i], 2);
        }
        if (t == 0) {
            float* dst = mp + (wn ? M_DOTB : M_DOTA);
#pragma unroll
            for (int mt = 0; mt < 2; mt++) {
                dst[m0w + mt * 16 + g] = dots[mt * 2];
                dst[m0w + mt * 16 + g + 8] = dots[mt * 2 + 1];
            }
        }
        __syncthreads();
        // agg atomics (float4)
        if (tile0 + row < EE) {
            int tg = s_tgt[row];
            float* dst = &g_agg[(size_t)tg * DD + half * 64];
            const float* src = &MS[row * 132 + half * 64];
#pragma unroll
            for (int q = 0; q < 16; q++) {
                float4 v = *(const float4*)(src + q * 4);
                atomicAdd((float4*)(dst + q * 4), v);
            }
        }
        // pw scalar path
        if (tid < 128 && tile0 + tid < EE) {
            float z = mp[M_DOTA + tid] + mp[M_DOTB + tid]
                      + mp[M_DIST + tid] * mp[M_PW1 + 128] + __ldg(pb1);
            float pwv = silu(z) * __ldg(pw2) + __ldg(pb2);
            int tg = s_tgt[tid];
            atomicAdd(&g_dp[tg * 2], mp[M_PUX + tid] * pwv);
            atomicAdd(&g_dp[tg * 2 + 1], mp[M_PUY + tid] * pwv);
        }
    } else {
        // node residual: x += msg + b2
#pragma unroll
        for (int mt = 0; mt < 2; mt++) {
            int rA = m0w + mt * 16 + g;
#pragma unroll
            for (int nt = 0; nt < 8; nt++) {
                int col = n0w + nt * 8 + 2 * t;
                float b2a = mp[M_B2 + col], b2b = mp[M_B2 + col + 1];
                int nA = tile0 + rA;
                if (nA < NN) {
                    float2* xp = (float2*)&g_x[(size_t)nA * DD + col];
                    float2 xv = *xp;
                    xv.x += acc[mt][nt][0] + b2a;
                    xv.y += acc[mt][nt][1] + b2b;
                    *xp = xv;
                }
                int nB = nA + 8;
                if (nB < NN) {
                    float2* xp = (float2*)&g_x[(size_t)nB * DD + col];
                    float2 xv = *xp;
                    xv.x += acc[mt][nt][2] + b2a;
                    xv.y += acc[mt][nt][3] + b2b;
                    *xp = xv;
                }
            }
        }
        if (tid < 128 && tile0 + tid < NN) {
            int n = tile0 + tid;
            g_p[n * 2] += g_dp[n * 2];
            g_p[n * 2 + 1] += g_dp[n * 2 + 1];
        }
    }
}

// ---------------------------------------------------------------------------
__global__ void ln_kernel(const float* __restrict__ gma, const float* __restrict__ bta,
                          float* __restrict__ out) {
    int warp = threadIdx.x >> 5, lane = threadIdx.x & 31;
    int n = blockIdx.x * 8 + warp;
    if (n >= NN) return;
    float4 v = *(const float4*)&g_x[(size_t)n * DD + lane * 4];
    float s = v.x + v.y + v.z + v.w;
    float sq = v.x * v.x + v.y * v.y + v.z * v.z + v.w * v.w;
#pragma unroll
    for (int o = 16; o > 0; o >>= 1) {
        s  += __shfl_xor_sync(0xFFFFFFFFu, s, o);
        sq += __shfl_xor_sync(0xFFFFFFFFu, sq, o);
    }
    float mu = s * (1.0f / 128.0f);
    float var = sq * (1.0f / 128.0f) - mu * mu;
    float r = rsqrtf(var + 1e-5f);
    float4 g4 = *(const float4*)&gma[lane * 4];
    float4 b4 = *(const float4*)&bta[lane * 4];
    float4 o4;
    o4.x = (v.x - mu) * r * g4.x + b4.x;
    o4.y = (v.y - mu) * r * g4.y + b4.y;
    o4.z = (v.z - mu) * r * g4.z + b4.z;
    o4.w = (v.w - mu) * r * g4.w + b4.w;
    *(float4*)&out[(size_t)n * DD + lane * 4] = o4;
}

// ---------------------------------------------------------------------------
extern "C" void kernel_launch(void* const* d_in, const int* in_sizes, int n_in,
                              void* d_out, int out_size) {
    (void)in_sizes; (void)n_in; (void)out_size;
    const float* nf   = (const float*)d_in[0];
    const float* pos  = (const float*)d_in[1];
    const float* npw  = (const float*)d_in[3];
    const float* npb  = (const float*)d_in[4];
    const float* ew1  = (const float*)d_in[7];
    const float* eb1  = (const float*)d_in[8];
    const float* ew2  = (const float*)d_in[9];
    const float* eb2  = (const float*)d_in[10];
    const float* nw1  = (const float*)d_in[11];
    const float* nb1  = (const float*)d_in[12];
    const float* nw2  = (const float*)d_in[13];
    const float* nb2  = (const float*)d_in[14];
    const float* pw1  = (const float*)d_in[15];
    const float* pb1  = (const float*)d_in[16];
    const float* pw2  = (const float*)d_in[17];
    const float* pb2  = (const float*)d_in[18];
    const float* lng  = (const float*)d_in[19];
    const float* lnb  = (const float*)d_in[20];
    const int*   eidx = (const int*)d_in[21];

    void* agg_ptr = nullptr;
    void* dp_ptr = nullptr;
    void* wt_ptr = nullptr;
    cudaGetSymbolAddress(&agg_ptr, g_agg);
    cudaGetSymbolAddress(&dp_ptr, g_dp);
    cudaGetSymbolAddress(&wt_ptr, g_wt);
    uint32_t* wt = (uint32_t*)wt_ptr;

    cudaFuncSetAttribute(layer_kernel<true>, cudaFuncAttributeMaxDynamicSharedMemorySize, SMEM_BYTES);
    cudaFuncSetAttribute(layer_kernel<false>, cudaFuncAttributeMaxDynamicSharedMemorySize, SMEM_BYTES);

    init_kernel<<<NN, DD>>>(nf, pos, npw, npb);

    for (int l = 0; l < LL; l++) {
        uint32_t* base = wt + (size_t)l * 98304;
        prep_w<<<4, 256>>>(ew1 + (size_t)l * 257 * 128, base);
        prep_w<<<2, 256>>>(ew2 + (size_t)l * 128 * 128, base + 32768);
        prep_w<<<4, 256>>>(nw1 + (size_t)l * 256 * 128, base + 49152);
        prep_w<<<2, 256>>>(nw2 + (size_t)l * 128 * 128, base + 81920);
    }

    for (int l = 0; l < LL; l++) {
        uint32_t* base = wt + (size_t)l * 98304;
        cudaMemsetAsync(agg_ptr, 0, (size_t)NN * DD * sizeof(float));
        cudaMemsetAsync(dp_ptr, 0, (size_t)NN * 2 * sizeof(float));
        layer_kernel<true><<<(EE + 127) / 128, 256, SMEM_BYTES>>>(
            base, base + 32768,
            ew1 + (size_t)l * 257 * 128 + 256 * 128,
            eb1 + l * 128, eb2 + l * 128,
            pw1 + l * 129, pb1 + l, pw2 + l, pb2 + l, eidx);
        layer_kernel<false><<<(NN + 127) / 128, 256, SMEM_BYTES>>>(
            base + 49152, base + 81920,
            nullptr,
            nb1 + l * 128, nb2 + l * 128,
            nullptr, nullptr, nullptr, nullptr, nullptr);
    }

    ln_kernel<<<(NN + 7) / 8, 256>>>(lng, lnb, (float*)d_out);
}